// round 10
// baseline (speedup 1.0000x reference)
#include <cuda_runtime.h>
#include <cuda_fp16.h>
#include <cstdint>

#define DN 128              // embedding dim
#define MAXN 200002         // USERS + ITEMS
#define MAXNNZ 2000000      // 2 * E

#define SCAN_BLK 256
#define SCAN_IPT 16
#define SCAN_CHUNK (SCAN_BLK * SCAN_IPT)   // 4096
#define MAX_SCAN_BLOCKS 64

// ---- static device scratch (no allocation allowed) ----
__device__ __half g_xe[(size_t)MAXN * DN];    // emb in fp16
__device__ __half g_x1[(size_t)MAXN * DN];    // layer-1 out
__device__ __half g_x2[(size_t)MAXN * DN];    // layer-2 out
__device__ int   g_deg[MAXN];
__device__ int   g_rowptr[MAXN];
__device__ int   g_cursor[MAXN];
__device__ int   g_bsum[MAX_SCAN_BLOCKS];
__device__ int2  g_edge[MAXNNZ];              // (col, float_bits(val)) grouped by row

// ---------------------------------------------------------------------------
// CSR build
// ---------------------------------------------------------------------------
__global__ void zero_deg_kernel(int n) {
    int i = blockIdx.x * blockDim.x + threadIdx.x;
    if (i < n) g_deg[i] = 0;
}

__global__ void hist_kernel(const int* __restrict__ rows, int nnz) {
    int e = blockIdx.x * blockDim.x + threadIdx.x;
    if (e < nnz) atomicAdd(&g_deg[rows[e]], 1);
}

__global__ void scan_reduce_kernel(int n) {
    __shared__ int s[SCAN_BLK];
    int base = blockIdx.x * SCAN_CHUNK + threadIdx.x * SCAN_IPT;
    int sum = 0;
#pragma unroll
    for (int i = 0; i < SCAN_IPT; i++) {
        int idx = base + i;
        if (idx < n) sum += g_deg[idx];
    }
    s[threadIdx.x] = sum;
    __syncthreads();
    for (int off = SCAN_BLK / 2; off > 0; off >>= 1) {
        if (threadIdx.x < off) s[threadIdx.x] += s[threadIdx.x + off];
        __syncthreads();
    }
    if (threadIdx.x == 0) g_bsum[blockIdx.x] = s[0];
}

__global__ void scan_top_kernel(int nb) {
    __shared__ int s[64];
    int t = threadIdx.x;
    int own = (t < nb) ? g_bsum[t] : 0;
    s[t] = own;
    __syncthreads();
#pragma unroll
    for (int o = 1; o < 64; o <<= 1) {
        int v = (t >= o) ? s[t - o] : 0;
        __syncthreads();
        s[t] += v;
        __syncthreads();
    }
    if (t < nb) g_bsum[t] = s[t] - own;   // exclusive
}

__global__ void scan_down_kernel(int n) {
    int tid = threadIdx.x;
    int base = blockIdx.x * SCAN_CHUNK + tid * SCAN_IPT;
    int local[SCAN_IPT];
    int sum = 0;
#pragma unroll
    for (int i = 0; i < SCAN_IPT; i++) {
        int idx = base + i;
        int v = (idx < n) ? g_deg[idx] : 0;
        local[i] = sum;
        sum += v;
    }
    int lane = tid & 31, wid = tid >> 5;
    int v = sum;
#pragma unroll
    for (int o = 1; o < 32; o <<= 1) {
        int t = __shfl_up_sync(0xFFFFFFFFu, v, o);
        if (lane >= o) v += t;
    }
    __shared__ int wsum[SCAN_BLK / 32];
    if (lane == 31) wsum[wid] = v;
    __syncthreads();
    if (tid < SCAN_BLK / 32) {
        int w = wsum[tid];
#pragma unroll
        for (int o = 1; o < SCAN_BLK / 32; o <<= 1) {
            int t = __shfl_up_sync(0xFFu, w, o);
            if (tid >= o) w += t;
        }
        wsum[tid] = w;
    }
    __syncthreads();
    int thread_excl = v - sum + (wid ? wsum[wid - 1] : 0);
    int off = thread_excl + g_bsum[blockIdx.x];
#pragma unroll
    for (int i = 0; i < SCAN_IPT; i++) {
        int idx = base + i;
        if (idx < n) {
            int p = off + local[i];
            g_rowptr[idx] = p;
            g_cursor[idx] = p;
        }
    }
}

__global__ void scatter_kernel(const int* __restrict__ rows,
                               const int* __restrict__ cols,
                               const float* __restrict__ vals,
                               int nnz) {
    int e = blockIdx.x * blockDim.x + threadIdx.x;
    if (e >= nnz) return;
    int r = rows[e];
    int pos = atomicAdd(&g_cursor[r], 1);
    g_edge[pos] = make_int2(cols[e], __float_as_int(vals[e]));
}

// ---------------------------------------------------------------------------
// emb (f32) -> f16
// ---------------------------------------------------------------------------
__global__ void f2h_kernel(const float4* __restrict__ src,
                           uint2* __restrict__ dst, int total4) {
    int i = blockIdx.x * blockDim.x + threadIdx.x;
    if (i >= total4) return;
    float4 v = src[i];
    __half2 a = __float22half2_rn(make_float2(v.x, v.y));
    __half2 b = __float22half2_rn(make_float2(v.z, v.w));
    uint2 r;
    r.x = *reinterpret_cast<unsigned int*>(&a);
    r.y = *reinterpret_cast<unsigned int*>(&b);
    dst[i] = r;
}

// ---------------------------------------------------------------------------
// pull SpMM, fp16 operand, fp32 accumulation. Warp per row.
// 8-wide edge unroll -> 8 independent gathers in flight (MLP=8).
// ---------------------------------------------------------------------------
__device__ __forceinline__ float2 h2f_lo(unsigned u) {
    __half2 h = *reinterpret_cast<__half2*>(&u);
    return __half22float2(h);
}

template <bool FUSE>
__global__ void __launch_bounds__(256) spmm_half_kernel(
        const uint2* __restrict__ x,
        uint2* __restrict__ yh,
        const float4* __restrict__ emb,
        const uint2* __restrict__ x1,
        const uint2* __restrict__ x2,
        float4* __restrict__ outf,
        int n) {
    int w = (blockIdx.x * blockDim.x + threadIdx.x) >> 5;
    int lane = threadIdx.x & 31;
    if (w >= n) return;

    int start = g_rowptr[w];
    int end = start + g_deg[w];

    float a0x = 0.f, a0y = 0.f, a0z = 0.f, a0w = 0.f;
    float a1x = 0.f, a1y = 0.f, a1z = 0.f, a1w = 0.f;

    int e = start;
    // 8-wide: issue all 8 gathers before consuming any
    for (; e + 8 <= end; e += 8) {
        int2 ed[8];
        uint2 m[8];
#pragma unroll
        for (int j = 0; j < 8; j++) ed[j] = g_edge[e + j];
#pragma unroll
        for (int j = 0; j < 8; j++)
            m[j] = __ldg(x + (size_t)ed[j].x * 32 + lane);
#pragma unroll
        for (int j = 0; j < 8; j++) {
            float v = __int_as_float(ed[j].y);
            float2 fa = h2f_lo(m[j].x), fb = h2f_lo(m[j].y);
            if (j & 1) {
                a1x += v * fa.x; a1y += v * fa.y; a1z += v * fb.x; a1w += v * fb.y;
            } else {
                a0x += v * fa.x; a0y += v * fa.y; a0z += v * fb.x; a0w += v * fb.y;
            }
        }
    }
    // 4-wide remainder
    if (e + 4 <= end) {
        int2 ed[4];
        uint2 m[4];
#pragma unroll
        for (int j = 0; j < 4; j++) ed[j] = g_edge[e + j];
#pragma unroll
        for (int j = 0; j < 4; j++)
            m[j] = __ldg(x + (size_t)ed[j].x * 32 + lane);
#pragma unroll
        for (int j = 0; j < 4; j++) {
            float v = __int_as_float(ed[j].y);
            float2 fa = h2f_lo(m[j].x), fb = h2f_lo(m[j].y);
            if (j & 1) {
                a1x += v * fa.x; a1y += v * fa.y; a1z += v * fb.x; a1w += v * fb.y;
            } else {
                a0x += v * fa.x; a0y += v * fa.y; a0z += v * fb.x; a0w += v * fb.y;
            }
        }
        e += 4;
    }
    if (e + 2 <= end) {
        int2 e0 = g_edge[e];
        int2 e1 = g_edge[e + 1];
        uint2 m0 = __ldg(x + (size_t)e0.x * 32 + lane);
        uint2 m1 = __ldg(x + (size_t)e1.x * 32 + lane);
        float v0 = __int_as_float(e0.y);
        float v1 = __int_as_float(e1.y);
        float2 fa = h2f_lo(m0.x), fb = h2f_lo(m0.y);
        a0x += v0 * fa.x; a0y += v0 * fa.y; a0z += v0 * fb.x; a0w += v0 * fb.y;
        float2 fc = h2f_lo(m1.x), fd = h2f_lo(m1.y);
        a1x += v1 * fc.x; a1y += v1 * fc.y; a1z += v1 * fd.x; a1w += v1 * fd.y;
        e += 2;
    }
    if (e < end) {
        int2 e0 = g_edge[e];
        uint2 m0 = __ldg(x + (size_t)e0.x * 32 + lane);
        float v0 = __int_as_float(e0.y);
        float2 fa = h2f_lo(m0.x), fb = h2f_lo(m0.y);
        a0x += v0 * fa.x; a0y += v0 * fa.y; a0z += v0 * fb.x; a0w += v0 * fb.y;
    }

    float rx = a0x + a1x, ry = a0y + a1y, rz = a0z + a1z, rw = a0w + a1w;

    size_t oidx = (size_t)w * 32 + lane;
    if (FUSE) {
        float4 eb = __ldg(emb + oidx);
        uint2 u1 = __ldg(x1 + oidx);
        uint2 u2 = __ldg(x2 + oidx);
        float2 b10 = h2f_lo(u1.x), b11 = h2f_lo(u1.y);
        float2 b20 = h2f_lo(u2.x), b21 = h2f_lo(u2.y);
        float4 o;
        o.x = (rx + eb.x + b10.x + b20.x) * 0.25f;
        o.y = (ry + eb.y + b10.y + b20.y) * 0.25f;
        o.z = (rz + eb.z + b11.x + b21.x) * 0.25f;
        o.w = (rw + eb.w + b11.y + b21.y) * 0.25f;
        outf[oidx] = o;
    } else {
        __half2 ha = __float22half2_rn(make_float2(rx, ry));
        __half2 hb = __float22half2_rn(make_float2(rz, rw));
        uint2 r;
        r.x = *reinterpret_cast<unsigned int*>(&ha);
        r.y = *reinterpret_cast<unsigned int*>(&hb);
        yh[oidx] = r;
    }
}

// ---------------------------------------------------------------------------
extern "C" void kernel_launch(void* const* d_in, const int* in_sizes, int n_in,
                              void* d_out, int out_size) {
    const float* emb  = (const float*)d_in[0];
    const float* vals = (const float*)d_in[1];
    const int*   rows = (const int*)d_in[2];
    const int*   cols = (const int*)d_in[3];
    float* out = (float*)d_out;

    int nnz = in_sizes[1];
    int n   = in_sizes[0] / DN;

    __half* xe; __half* x1; __half* x2;
    cudaGetSymbolAddress((void**)&xe, g_xe);
    cudaGetSymbolAddress((void**)&x1, g_x1);
    cudaGetSymbolAddress((void**)&x2, g_x2);

    const int TB = 256;
    int total4 = in_sizes[0] / 4;
    int nb_scan     = (n + SCAN_CHUNK - 1) / SCAN_CHUNK;
    int deg_blocks  = (n + TB - 1) / TB;
    int edge_blocks = (nnz + TB - 1) / TB;
    int ew_blocks   = (total4 + TB - 1) / TB;
    int spmm_blocks = (n * 32 + TB - 1) / TB;

    // --- CSR build ---
    zero_deg_kernel<<<deg_blocks, TB>>>(n);
    hist_kernel<<<edge_blocks, TB>>>(rows, nnz);
    scan_reduce_kernel<<<nb_scan, SCAN_BLK>>>(n);
    scan_top_kernel<<<1, 64>>>(nb_scan);
    scan_down_kernel<<<nb_scan, SCAN_BLK>>>(n);
    scatter_kernel<<<edge_blocks, TB>>>(rows, cols, vals, nnz);

    // --- emb -> fp16 ---
    f2h_kernel<<<ew_blocks, TB>>>((const float4*)emb, (uint2*)xe, total4);

    // --- 3 layers ---
    spmm_half_kernel<false><<<spmm_blocks, TB>>>(
        (const uint2*)xe, (uint2*)x1, nullptr, nullptr, nullptr, nullptr, n);
    spmm_half_kernel<false><<<spmm_blocks, TB>>>(
        (const uint2*)x1, (uint2*)x2, nullptr, nullptr, nullptr, nullptr, n);
    spmm_half_kernel<true><<<spmm_blocks, TB>>>(
        (const uint2*)x2, nullptr,
        (const float4*)emb, (const uint2*)x1, (const uint2*)x2,
        (float4*)out, n);
}

// round 12
// speedup vs baseline: 1.0817x; 1.0817x over previous
#include <cuda_runtime.h>
#include <cuda_fp16.h>
#include <cstdint>

#define DN 128              // embedding dim
#define MAXN 200002         // USERS + ITEMS
#define MAXNNZ 2000000      // 2 * E

#define SCAN_BLK 256
#define SCAN_IPT 16
#define SCAN_CHUNK (SCAN_BLK * SCAN_IPT)   // 4096
#define MAX_SCAN_BLOCKS 64

// ---- static device scratch (no allocation allowed) ----
__device__ __half g_xe[(size_t)MAXN * DN];    // emb in fp16
__device__ __half g_x1[(size_t)MAXN * DN];    // layer-1 out
__device__ __half g_x2[(size_t)MAXN * DN];    // layer-2 out
__device__ int   g_deg[MAXN];
__device__ int   g_rowptr[MAXN];
__device__ int   g_cursor[MAXN];
__device__ int   g_bsum[MAX_SCAN_BLOCKS];
__device__ int2  g_edge[MAXNNZ];              // (col, float_bits(val)) grouped by row

// ---------------------------------------------------------------------------
// CSR build
// ---------------------------------------------------------------------------
__global__ void zero_deg_kernel(int n) {
    int i = blockIdx.x * blockDim.x + threadIdx.x;
    if (i < n) g_deg[i] = 0;
}

__global__ void hist_kernel(const int* __restrict__ rows, int nnz) {
    int e = blockIdx.x * blockDim.x + threadIdx.x;
    if (e < nnz) atomicAdd(&g_deg[rows[e]], 1);
}

__global__ void scan_reduce_kernel(int n) {
    __shared__ int s[SCAN_BLK];
    int base = blockIdx.x * SCAN_CHUNK + threadIdx.x * SCAN_IPT;
    int sum = 0;
#pragma unroll
    for (int i = 0; i < SCAN_IPT; i++) {
        int idx = base + i;
        if (idx < n) sum += g_deg[idx];
    }
    s[threadIdx.x] = sum;
    __syncthreads();
    for (int off = SCAN_BLK / 2; off > 0; off >>= 1) {
        if (threadIdx.x < off) s[threadIdx.x] += s[threadIdx.x + off];
        __syncthreads();
    }
    if (threadIdx.x == 0) g_bsum[blockIdx.x] = s[0];
}

__global__ void scan_top_kernel(int nb) {
    __shared__ int s[64];
    int t = threadIdx.x;
    int own = (t < nb) ? g_bsum[t] : 0;
    s[t] = own;
    __syncthreads();
#pragma unroll
    for (int o = 1; o < 64; o <<= 1) {
        int v = (t >= o) ? s[t - o] : 0;
        __syncthreads();
        s[t] += v;
        __syncthreads();
    }
    if (t < nb) g_bsum[t] = s[t] - own;   // exclusive
}

__global__ void scan_down_kernel(int n) {
    int tid = threadIdx.x;
    int base = blockIdx.x * SCAN_CHUNK + tid * SCAN_IPT;
    int local[SCAN_IPT];
    int sum = 0;
#pragma unroll
    for (int i = 0; i < SCAN_IPT; i++) {
        int idx = base + i;
        int v = (idx < n) ? g_deg[idx] : 0;
        local[i] = sum;
        sum += v;
    }
    int lane = tid & 31, wid = tid >> 5;
    int v = sum;
#pragma unroll
    for (int o = 1; o < 32; o <<= 1) {
        int t = __shfl_up_sync(0xFFFFFFFFu, v, o);
        if (lane >= o) v += t;
    }
    __shared__ int wsum[SCAN_BLK / 32];
    if (lane == 31) wsum[wid] = v;
    __syncthreads();
    if (tid < SCAN_BLK / 32) {
        int w = wsum[tid];
#pragma unroll
        for (int o = 1; o < SCAN_BLK / 32; o <<= 1) {
            int t = __shfl_up_sync(0xFFu, w, o);
            if (tid >= o) w += t;
        }
        wsum[tid] = w;
    }
    __syncthreads();
    int thread_excl = v - sum + (wid ? wsum[wid - 1] : 0);
    int off = thread_excl + g_bsum[blockIdx.x];
#pragma unroll
    for (int i = 0; i < SCAN_IPT; i++) {
        int idx = base + i;
        if (idx < n) {
            int p = off + local[i];
            g_rowptr[idx] = p;
            g_cursor[idx] = p;
        }
    }
}

__global__ void scatter_kernel(const int* __restrict__ rows,
                               const int* __restrict__ cols,
                               const float* __restrict__ vals,
                               int nnz) {
    int e = blockIdx.x * blockDim.x + threadIdx.x;
    if (e >= nnz) return;
    int r = rows[e];
    int pos = atomicAdd(&g_cursor[r], 1);
    g_edge[pos] = make_int2(cols[e], __float_as_int(vals[e]));
}

// ---------------------------------------------------------------------------
// emb (f32) -> f16
// ---------------------------------------------------------------------------
__global__ void f2h_kernel(const float4* __restrict__ src,
                           uint2* __restrict__ dst, int total4) {
    int i = blockIdx.x * blockDim.x + threadIdx.x;
    if (i >= total4) return;
    float4 v = src[i];
    __half2 a = __float22half2_rn(make_float2(v.x, v.y));
    __half2 b = __float22half2_rn(make_float2(v.z, v.w));
    uint2 r;
    r.x = *reinterpret_cast<unsigned int*>(&a);
    r.y = *reinterpret_cast<unsigned int*>(&b);
    dst[i] = r;
}

// ---------------------------------------------------------------------------
// pull SpMM, fp16 operand, fp32 accumulation.
// HALF-WARP (16 lanes) per row, uint4 gathers (16B/lane * 16 lanes = 256B row).
// 4-wide edge unroll per half-warp -> up to 8 gathers in flight per warp.
// ---------------------------------------------------------------------------
__device__ __forceinline__ float2 h2f_lo(unsigned u) {
    __half2 h = *reinterpret_cast<__half2*>(&u);
    return __half22float2(h);
}

__device__ __forceinline__ void acc8(float* a, uint4 m, float v) {
    float2 f0 = h2f_lo(m.x), f1 = h2f_lo(m.y), f2 = h2f_lo(m.z), f3 = h2f_lo(m.w);
    a[0] += v * f0.x; a[1] += v * f0.y;
    a[2] += v * f1.x; a[3] += v * f1.y;
    a[4] += v * f2.x; a[5] += v * f2.y;
    a[6] += v * f3.x; a[7] += v * f3.y;
}

template <bool FUSE>
__global__ void __launch_bounds__(256) spmm_hw_kernel(
        const uint4* __restrict__ x,          // fp16 activations, 16 uint4 per row
        uint4* __restrict__ yh,               // fp16 out (non-fused)
        const float4* __restrict__ emb,       // fp32 (fused only)
        const uint4* __restrict__ x1,         // fp16 (fused only)
        const uint4* __restrict__ x2,         // fp16 (fused only)
        float4* __restrict__ outf,            // fp32 out (fused only)
        int n) {
    int hw = (blockIdx.x * blockDim.x + threadIdx.x) >> 4;   // half-warp id = row
    int lane = threadIdx.x & 15;
    if (hw >= n) return;

    int start = g_rowptr[hw];
    int end = start + g_deg[hw];

    float a0[8] = {0.f, 0.f, 0.f, 0.f, 0.f, 0.f, 0.f, 0.f};
    float a1[8] = {0.f, 0.f, 0.f, 0.f, 0.f, 0.f, 0.f, 0.f};

    int e = start;
    for (; e + 4 <= end; e += 4) {
        int2 e0 = g_edge[e];
        int2 e1 = g_edge[e + 1];
        int2 e2 = g_edge[e + 2];
        int2 e3 = g_edge[e + 3];
        uint4 m0 = __ldg(x + (size_t)e0.x * 16 + lane);
        uint4 m1 = __ldg(x + (size_t)e1.x * 16 + lane);
        uint4 m2 = __ldg(x + (size_t)e2.x * 16 + lane);
        uint4 m3 = __ldg(x + (size_t)e3.x * 16 + lane);
        acc8(a0, m0, __int_as_float(e0.y));
        acc8(a1, m1, __int_as_float(e1.y));
        acc8(a0, m2, __int_as_float(e2.y));
        acc8(a1, m3, __int_as_float(e3.y));
    }
    if (e + 2 <= end) {
        int2 e0 = g_edge[e];
        int2 e1 = g_edge[e + 1];
        uint4 m0 = __ldg(x + (size_t)e0.x * 16 + lane);
        uint4 m1 = __ldg(x + (size_t)e1.x * 16 + lane);
        acc8(a0, m0, __int_as_float(e0.y));
        acc8(a1, m1, __int_as_float(e1.y));
        e += 2;
    }
    if (e < end) {
        int2 e0 = g_edge[e];
        uint4 m0 = __ldg(x + (size_t)e0.x * 16 + lane);
        acc8(a0, m0, __int_as_float(e0.y));
    }

    float r[8];
#pragma unroll
    for (int j = 0; j < 8; j++) r[j] = a0[j] + a1[j];

    if (FUSE) {
        // lane owns dims [lane*8, lane*8+8) -> two float4 slots
        size_t o = (size_t)hw * 32 + lane * 2;
        float4 eb0 = __ldg(emb + o);
        float4 eb1 = __ldg(emb + o + 1);
        uint4 u1 = __ldg(x1 + (size_t)hw * 16 + lane);
        uint4 u2 = __ldg(x2 + (size_t)hw * 16 + lane);
        float2 p10 = h2f_lo(u1.x), p11 = h2f_lo(u1.y), p12 = h2f_lo(u1.z), p13 = h2f_lo(u1.w);
        float2 p20 = h2f_lo(u2.x), p21 = h2f_lo(u2.y), p22 = h2f_lo(u2.z), p23 = h2f_lo(u2.w);
        float4 o0, o1;
        o0.x = (r[0] + eb0.x + p10.x + p20.x) * 0.25f;
        o0.y = (r[1] + eb0.y + p10.y + p20.y) * 0.25f;
        o0.z = (r[2] + eb0.z + p11.x + p21.x) * 0.25f;
        o0.w = (r[3] + eb0.w + p11.y + p21.y) * 0.25f;
        o1.x = (r[4] + eb1.x + p12.x + p22.x) * 0.25f;
        o1.y = (r[5] + eb1.y + p12.y + p22.y) * 0.25f;
        o1.z = (r[6] + eb1.z + p13.x + p23.x) * 0.25f;
        o1.w = (r[7] + eb1.w + p13.y + p23.y) * 0.25f;
        outf[o] = o0;
        outf[o + 1] = o1;
    } else {
        __half2 h0 = __float22half2_rn(make_float2(r[0], r[1]));
        __half2 h1 = __float22half2_rn(make_float2(r[2], r[3]));
        __half2 h2 = __float22half2_rn(make_float2(r[4], r[5]));
        __half2 h3 = __float22half2_rn(make_float2(r[6], r[7]));
        uint4 out;
        out.x = *reinterpret_cast<unsigned int*>(&h0);
        out.y = *reinterpret_cast<unsigned int*>(&h1);
        out.z = *reinterpret_cast<unsigned int*>(&h2);
        out.w = *reinterpret_cast<unsigned int*>(&h3);
        yh[(size_t)hw * 16 + lane] = out;
    }
}

// ---------------------------------------------------------------------------
extern "C" void kernel_launch(void* const* d_in, const int* in_sizes, int n_in,
                              void* d_out, int out_size) {
    const float* emb  = (const float*)d_in[0];
    const float* vals = (const float*)d_in[1];
    const int*   rows = (const int*)d_in[2];
    const int*   cols = (const int*)d_in[3];
    float* out = (float*)d_out;

    int nnz = in_sizes[1];
    int n   = in_sizes[0] / DN;

    __half* xe; __half* x1; __half* x2;
    cudaGetSymbolAddress((void**)&xe, g_xe);
    cudaGetSymbolAddress((void**)&x1, g_x1);
    cudaGetSymbolAddress((void**)&x2, g_x2);

    const int TB = 256;
    int total4 = in_sizes[0] / 4;
    int nb_scan     = (n + SCAN_CHUNK - 1) / SCAN_CHUNK;
    int deg_blocks  = (n + TB - 1) / TB;
    int edge_blocks = (nnz + TB - 1) / TB;
    int ew_blocks   = (total4 + TB - 1) / TB;
    int spmm_blocks = (n * 16 + TB - 1) / TB;   // 16 threads per row now

    // --- CSR build ---
    zero_deg_kernel<<<deg_blocks, TB>>>(n);
    hist_kernel<<<edge_blocks, TB>>>(rows, nnz);
    scan_reduce_kernel<<<nb_scan, SCAN_BLK>>>(n);
    scan_top_kernel<<<1, 64>>>(nb_scan);
    scan_down_kernel<<<nb_scan, SCAN_BLK>>>(n);
    scatter_kernel<<<edge_blocks, TB>>>(rows, cols, vals, nnz);

    // --- emb -> fp16 ---
    f2h_kernel<<<ew_blocks, TB>>>((const float4*)emb, (uint2*)xe, total4);

    // --- 3 layers ---
    spmm_hw_kernel<false><<<spmm_blocks, TB>>>(
        (const uint4*)xe, (uint4*)x1, nullptr, nullptr, nullptr, nullptr, n);
    spmm_hw_kernel<false><<<spmm_blocks, TB>>>(
        (const uint4*)x1, (uint4*)x2, nullptr, nullptr, nullptr, nullptr, n);
    spmm_hw_kernel<true><<<spmm_blocks, TB>>>(
        (const uint4*)x2, nullptr,
        (const float4*)emb, (const uint4*)x1, (const uint4*)x2,
        (float4*)out, n);
}

// round 13
// speedup vs baseline: 1.1225x; 1.0377x over previous
#include <cuda_runtime.h>
#include <cuda_fp16.h>
#include <cstdint>

#define DN 128              // embedding dim
#define MAXN 200002         // USERS + ITEMS
#define MAXNNZ 2000000      // 2 * E

#define SCAN_BLK 256
#define SCAN_IPT 16
#define SCAN_CHUNK (SCAN_BLK * SCAN_IPT)   // 4096
#define MAX_SCAN_BLOCKS 64

// ---- static device scratch (no allocation allowed) ----
__device__ __half g_xe[(size_t)MAXN * DN];    // emb in fp16
__device__ __half g_x1[(size_t)MAXN * DN];    // layer-1 out
__device__ __half g_x2[(size_t)MAXN * DN];    // layer-2 out
__device__ int   g_deg[MAXN];
__device__ int   g_rowptr[MAXN];
__device__ int   g_cursor[MAXN];
__device__ int   g_bsum[MAX_SCAN_BLOCKS];
__device__ int2  g_edge[MAXNNZ];              // (col, float_bits(val)) grouped by row

// ---- cache-policy helpers ----
__device__ __forceinline__ int2 ldcs_int2(const int2* p) {
    int2 r;
    asm volatile("ld.global.cs.v2.s32 {%0, %1}, [%2];"
                 : "=r"(r.x), "=r"(r.y) : "l"(p));
    return r;
}
__device__ __forceinline__ void stcs_uint2(uint2* p, uint2 v) {
    asm volatile("st.global.cs.v2.u32 [%0], {%1, %2};"
                 :: "l"(p), "r"(v.x), "r"(v.y) : "memory");
}
__device__ __forceinline__ void stcs_float4(float4* p, float4 v) {
    asm volatile("st.global.cs.v4.f32 [%0], {%1, %2, %3, %4};"
                 :: "l"(p), "f"(v.x), "f"(v.y), "f"(v.z), "f"(v.w) : "memory");
}

// ---------------------------------------------------------------------------
// CSR build
// ---------------------------------------------------------------------------
__global__ void zero_deg_kernel(int n) {
    int i = blockIdx.x * blockDim.x + threadIdx.x;
    if (i < n) g_deg[i] = 0;
}

__global__ void hist_kernel(const int* __restrict__ rows, int nnz) {
    int e = blockIdx.x * blockDim.x + threadIdx.x;
    if (e < nnz) atomicAdd(&g_deg[rows[e]], 1);
}

__global__ void scan_reduce_kernel(int n) {
    __shared__ int s[SCAN_BLK];
    int base = blockIdx.x * SCAN_CHUNK + threadIdx.x * SCAN_IPT;
    int sum = 0;
#pragma unroll
    for (int i = 0; i < SCAN_IPT; i++) {
        int idx = base + i;
        if (idx < n) sum += g_deg[idx];
    }
    s[threadIdx.x] = sum;
    __syncthreads();
    for (int off = SCAN_BLK / 2; off > 0; off >>= 1) {
        if (threadIdx.x < off) s[threadIdx.x] += s[threadIdx.x + off];
        __syncthreads();
    }
    if (threadIdx.x == 0) g_bsum[blockIdx.x] = s[0];
}

__global__ void scan_top_kernel(int nb) {
    __shared__ int s[64];
    int t = threadIdx.x;
    int own = (t < nb) ? g_bsum[t] : 0;
    s[t] = own;
    __syncthreads();
#pragma unroll
    for (int o = 1; o < 64; o <<= 1) {
        int v = (t >= o) ? s[t - o] : 0;
        __syncthreads();
        s[t] += v;
        __syncthreads();
    }
    if (t < nb) g_bsum[t] = s[t] - own;   // exclusive
}

__global__ void scan_down_kernel(int n) {
    int tid = threadIdx.x;
    int base = blockIdx.x * SCAN_CHUNK + tid * SCAN_IPT;
    int local[SCAN_IPT];
    int sum = 0;
#pragma unroll
    for (int i = 0; i < SCAN_IPT; i++) {
        int idx = base + i;
        int v = (idx < n) ? g_deg[idx] : 0;
        local[i] = sum;
        sum += v;
    }
    int lane = tid & 31, wid = tid >> 5;
    int v = sum;
#pragma unroll
    for (int o = 1; o < 32; o <<= 1) {
        int t = __shfl_up_sync(0xFFFFFFFFu, v, o);
        if (lane >= o) v += t;
    }
    __shared__ int wsum[SCAN_BLK / 32];
    if (lane == 31) wsum[wid] = v;
    __syncthreads();
    if (tid < SCAN_BLK / 32) {
        int w = wsum[tid];
#pragma unroll
        for (int o = 1; o < SCAN_BLK / 32; o <<= 1) {
            int t = __shfl_up_sync(0xFFu, w, o);
            if (tid >= o) w += t;
        }
        wsum[tid] = w;
    }
    __syncthreads();
    int thread_excl = v - sum + (wid ? wsum[wid - 1] : 0);
    int off = thread_excl + g_bsum[blockIdx.x];
#pragma unroll
    for (int i = 0; i < SCAN_IPT; i++) {
        int idx = base + i;
        if (idx < n) {
            int p = off + local[i];
            g_rowptr[idx] = p;
            g_cursor[idx] = p;
        }
    }
}

__global__ void scatter_kernel(const int* __restrict__ rows,
                               const int* __restrict__ cols,
                               const float* __restrict__ vals,
                               int nnz) {
    int e = blockIdx.x * blockDim.x + threadIdx.x;
    if (e >= nnz) return;
    int r = rows[e];
    int pos = atomicAdd(&g_cursor[r], 1);
    g_edge[pos] = make_int2(cols[e], __float_as_int(vals[e]));
}

// ---------------------------------------------------------------------------
// emb (f32) -> f16
// ---------------------------------------------------------------------------
__global__ void f2h_kernel(const float4* __restrict__ src,
                           uint2* __restrict__ dst, int total4) {
    int i = blockIdx.x * blockDim.x + threadIdx.x;
    if (i >= total4) return;
    float4 v = src[i];
    __half2 a = __float22half2_rn(make_float2(v.x, v.y));
    __half2 b = __float22half2_rn(make_float2(v.z, v.w));
    uint2 r;
    r.x = *reinterpret_cast<unsigned int*>(&a);
    r.y = *reinterpret_cast<unsigned int*>(&b);
    dst[i] = r;
}

// ---------------------------------------------------------------------------
// pull SpMM, fp16 operand, fp32 accumulation. Warp per row, 4-wide unroll.
// Cache policy: gathers via __ldg (keep x L2-resident), edge reads .cs
// (read-once stream), y stores .cs (write stream, don't evict x).
// ---------------------------------------------------------------------------
__device__ __forceinline__ float2 h2f_lo(unsigned u) {
    __half2 h = *reinterpret_cast<__half2*>(&u);
    return __half22float2(h);
}

template <bool FUSE>
__global__ void __launch_bounds__(256) spmm_half_kernel(
        const uint2* __restrict__ x,
        uint2* __restrict__ yh,
        const float4* __restrict__ emb,
        const uint2* __restrict__ x1,
        const uint2* __restrict__ x2,
        float4* __restrict__ outf,
        int n) {
    int w = (blockIdx.x * blockDim.x + threadIdx.x) >> 5;
    int lane = threadIdx.x & 31;
    if (w >= n) return;

    int start = g_rowptr[w];
    int end = start + g_deg[w];

    float a0x = 0.f, a0y = 0.f, a0z = 0.f, a0w = 0.f;
    float a1x = 0.f, a1y = 0.f, a1z = 0.f, a1w = 0.f;

    int e = start;
    // 4-wide: issue all 4 gathers before consuming any
    for (; e + 4 <= end; e += 4) {
        int2 e0 = ldcs_int2(&g_edge[e]);
        int2 e1 = ldcs_int2(&g_edge[e + 1]);
        int2 e2 = ldcs_int2(&g_edge[e + 2]);
        int2 e3 = ldcs_int2(&g_edge[e + 3]);
        uint2 m0 = __ldg(x + (size_t)e0.x * 32 + lane);
        uint2 m1 = __ldg(x + (size_t)e1.x * 32 + lane);
        uint2 m2 = __ldg(x + (size_t)e2.x * 32 + lane);
        uint2 m3 = __ldg(x + (size_t)e3.x * 32 + lane);
        float v0 = __int_as_float(e0.y);
        float v1 = __int_as_float(e1.y);
        float v2 = __int_as_float(e2.y);
        float v3 = __int_as_float(e3.y);
        {
            float2 fa = h2f_lo(m0.x), fb = h2f_lo(m0.y);
            a0x += v0 * fa.x; a0y += v0 * fa.y; a0z += v0 * fb.x; a0w += v0 * fb.y;
        }
        {
            float2 fa = h2f_lo(m1.x), fb = h2f_lo(m1.y);
            a1x += v1 * fa.x; a1y += v1 * fa.y; a1z += v1 * fb.x; a1w += v1 * fb.y;
        }
        {
            float2 fa = h2f_lo(m2.x), fb = h2f_lo(m2.y);
            a0x += v2 * fa.x; a0y += v2 * fa.y; a0z += v2 * fb.x; a0w += v2 * fb.y;
        }
        {
            float2 fa = h2f_lo(m3.x), fb = h2f_lo(m3.y);
            a1x += v3 * fa.x; a1y += v3 * fa.y; a1z += v3 * fb.x; a1w += v3 * fb.y;
        }
    }
    if (e + 2 <= end) {
        int2 e0 = ldcs_int2(&g_edge[e]);
        int2 e1 = ldcs_int2(&g_edge[e + 1]);
        uint2 m0 = __ldg(x + (size_t)e0.x * 32 + lane);
        uint2 m1 = __ldg(x + (size_t)e1.x * 32 + lane);
        float v0 = __int_as_float(e0.y);
        float v1 = __int_as_float(e1.y);
        float2 fa = h2f_lo(m0.x), fb = h2f_lo(m0.y);
        a0x += v0 * fa.x; a0y += v0 * fa.y; a0z += v0 * fb.x; a0w += v0 * fb.y;
        float2 fc = h2f_lo(m1.x), fd = h2f_lo(m1.y);
        a1x += v1 * fc.x; a1y += v1 * fc.y; a1z += v1 * fd.x; a1w += v1 * fd.y;
        e += 2;
    }
    if (e < end) {
        int2 e0 = ldcs_int2(&g_edge[e]);
        uint2 m0 = __ldg(x + (size_t)e0.x * 32 + lane);
        float v0 = __int_as_float(e0.y);
        float2 fa = h2f_lo(m0.x), fb = h2f_lo(m0.y);
        a0x += v0 * fa.x; a0y += v0 * fa.y; a0z += v0 * fb.x; a0w += v0 * fb.y;
    }

    float rx = a0x + a1x, ry = a0y + a1y, rz = a0z + a1z, rw = a0w + a1w;

    size_t oidx = (size_t)w * 32 + lane;
    if (FUSE) {
        float4 eb = __ldg(emb + oidx);
        uint2 u1 = __ldg(x1 + oidx);
        uint2 u2 = __ldg(x2 + oidx);
        float2 b10 = h2f_lo(u1.x), b11 = h2f_lo(u1.y);
        float2 b20 = h2f_lo(u2.x), b21 = h2f_lo(u2.y);
        float4 o;
        o.x = (rx + eb.x + b10.x + b20.x) * 0.25f;
        o.y = (ry + eb.y + b10.y + b20.y) * 0.25f;
        o.z = (rz + eb.z + b11.x + b21.x) * 0.25f;
        o.w = (rw + eb.w + b11.y + b21.y) * 0.25f;
        stcs_float4(outf + oidx, o);
    } else {
        __half2 ha = __float22half2_rn(make_float2(rx, ry));
        __half2 hb = __float22half2_rn(make_float2(rz, rw));
        uint2 r;
        r.x = *reinterpret_cast<unsigned int*>(&ha);
        r.y = *reinterpret_cast<unsigned int*>(&hb);
        stcs_uint2(yh + oidx, r);
    }
}

// ---------------------------------------------------------------------------
extern "C" void kernel_launch(void* const* d_in, const int* in_sizes, int n_in,
                              void* d_out, int out_size) {
    const float* emb  = (const float*)d_in[0];
    const float* vals = (const float*)d_in[1];
    const int*   rows = (const int*)d_in[2];
    const int*   cols = (const int*)d_in[3];
    float* out = (float*)d_out;

    int nnz = in_sizes[1];
    int n   = in_sizes[0] / DN;

    __half* xe; __half* x1; __half* x2;
    cudaGetSymbolAddress((void**)&xe, g_xe);
    cudaGetSymbolAddress((void**)&x1, g_x1);
    cudaGetSymbolAddress((void**)&x2, g_x2);

    const int TB = 256;
    int total4 = in_sizes[0] / 4;
    int nb_scan     = (n + SCAN_CHUNK - 1) / SCAN_CHUNK;
    int deg_blocks  = (n + TB - 1) / TB;
    int edge_blocks = (nnz + TB - 1) / TB;
    int ew_blocks   = (total4 + TB - 1) / TB;
    int spmm_blocks = (n * 32 + TB - 1) / TB;

    // --- CSR build ---
    zero_deg_kernel<<<deg_blocks, TB>>>(n);
    hist_kernel<<<edge_blocks, TB>>>(rows, nnz);
    scan_reduce_kernel<<<nb_scan, SCAN_BLK>>>(n);
    scan_top_kernel<<<1, 64>>>(nb_scan);
    scan_down_kernel<<<nb_scan, SCAN_BLK>>>(n);
    scatter_kernel<<<edge_blocks, TB>>>(rows, cols, vals, nnz);

    // --- emb -> fp16 ---
    f2h_kernel<<<ew_blocks, TB>>>((const float4*)emb, (uint2*)xe, total4);

    // --- 3 layers ---
    spmm_half_kernel<false><<<spmm_blocks, TB>>>(
        (const uint2*)xe, (uint2*)x1, nullptr, nullptr, nullptr, nullptr, n);
    spmm_half_kernel<false><<<spmm_blocks, TB>>>(
        (const uint2*)x1, (uint2*)x2, nullptr, nullptr, nullptr, nullptr, n);
    spmm_half_kernel<true><<<spmm_blocks, TB>>>(
        (const uint2*)x2, nullptr,
        (const float4*)emb, (const uint2*)x1, (const uint2*)x2,
        (float4*)out, n);
}

// round 14
// speedup vs baseline: 1.2195x; 1.0864x over previous
#include <cuda_runtime.h>
#include <cuda_fp16.h>
#include <cstdint>

#define DN 128              // embedding dim
#define MAXN 200002         // USERS + ITEMS
#define MAXNNZ 2000000      // 2 * E

#define SCAN_BLK 256
#define SCAN_IPT 16
#define SCAN_CHUNK (SCAN_BLK * SCAN_IPT)   // 4096
#define MAX_SCAN_BLOCKS 64                 // ceil(200002/4096) = 49

// ---- static device scratch (no allocation allowed) ----
__device__ __half g_xe[(size_t)MAXN * DN];    // emb in fp16
__device__ __half g_x1[(size_t)MAXN * DN];    // layer-1 out
__device__ __half g_x2[(size_t)MAXN * DN];    // layer-2 out
__device__ int   g_deg[MAXN];
__device__ int   g_rowptr[MAXN];
__device__ int   g_cursor[MAXN];
__device__ unsigned long long g_scan_state[MAX_SCAN_BLOCKS]; // bit63=published, low bits=aggregate
__device__ int2  g_edge[MAXNNZ];              // (col, float_bits(val)) grouped by row

// ---------------------------------------------------------------------------
// zero: deg counters + scan state
// ---------------------------------------------------------------------------
__global__ void zero_kernel(int n) {
    int i = blockIdx.x * blockDim.x + threadIdx.x;
    if (i < n) g_deg[i] = 0;
    if (i < MAX_SCAN_BLOCKS) g_scan_state[i] = 0ull;
}

// ---------------------------------------------------------------------------
// fused: blocks [0, ew_blocks) convert emb f32->f16; the rest histogram rows.
// Both independent; both only require zero_kernel to have completed.
// ---------------------------------------------------------------------------
__global__ void f2h_hist_kernel(const float4* __restrict__ src,
                                uint2* __restrict__ dst, int total4,
                                int ew_blocks,
                                const int* __restrict__ rows, int nnz) {
    if (blockIdx.x < (unsigned)ew_blocks) {
        int i = blockIdx.x * blockDim.x + threadIdx.x;
        if (i >= total4) return;
        float4 v = src[i];
        __half2 a = __float22half2_rn(make_float2(v.x, v.y));
        __half2 b = __float22half2_rn(make_float2(v.z, v.w));
        uint2 r;
        r.x = *reinterpret_cast<unsigned int*>(&a);
        r.y = *reinterpret_cast<unsigned int*>(&b);
        dst[i] = r;
    } else {
        int e = (blockIdx.x - ew_blocks) * blockDim.x + threadIdx.x;
        if (e < nnz) atomicAdd(&g_deg[rows[e]], 1);
    }
}

// ---------------------------------------------------------------------------
// single-pass exclusive scan of g_deg -> g_rowptr/g_cursor (decoupled lookback,
// aggregates only: each block sums ALL predecessor aggregates warp-parallel).
// Aggregate is self-contained in one 64-bit word -> relaxed atomics are enough.
// ---------------------------------------------------------------------------
__global__ void scan_fused_kernel(int n) {
    int tid = threadIdx.x, b = blockIdx.x;
    int base = b * SCAN_CHUNK + tid * SCAN_IPT;
    int local[SCAN_IPT];
    int sum = 0;
#pragma unroll
    for (int i = 0; i < SCAN_IPT; i++) {
        int idx = base + i;
        int v = (idx < n) ? g_deg[idx] : 0;
        local[i] = sum;        // exclusive within thread
        sum += v;
    }
    int lane = tid & 31, wid = tid >> 5;
    int v = sum;
#pragma unroll
    for (int o = 1; o < 32; o <<= 1) {
        int t = __shfl_up_sync(0xFFFFFFFFu, v, o);
        if (lane >= o) v += t;
    }
    __shared__ int wsum[SCAN_BLK / 32];
    __shared__ int s_base;
    if (lane == 31) wsum[wid] = v;
    __syncthreads();
    if (tid < SCAN_BLK / 32) {
        int w = wsum[tid];
#pragma unroll
        for (int o = 1; o < SCAN_BLK / 32; o <<= 1) {
            int t = __shfl_up_sync(0xFFu, w, o);
            if (tid >= o) w += t;
        }
        wsum[tid] = w;
        if (tid == SCAN_BLK / 32 - 1) {
            // publish this block's aggregate (flag in bit 63)
            atomicExch(&g_scan_state[b], (1ull << 63) | (unsigned long long)(unsigned)w);
        }
    }
    __syncthreads();
    // lookback: warp 0 sums aggregates of blocks [0, b), lanes in parallel
    if (wid == 0) {
        unsigned long long acc = 0;
        for (int i = lane; i < b; i += 32) {
            unsigned long long st;
            do {
                st = atomicAdd(&g_scan_state[i], 0ull);
            } while (!(st >> 63));
            acc += st & 0x7FFFFFFFFFFFFFFFull;
        }
#pragma unroll
        for (int o = 16; o > 0; o >>= 1)
            acc += __shfl_down_sync(0xFFFFFFFFu, acc, o);
        if (lane == 0) s_base = (int)acc;
    }
    __syncthreads();
    int thread_excl = v - sum + (wid ? wsum[wid - 1] : 0);
    int off = thread_excl + s_base;
#pragma unroll
    for (int i = 0; i < SCAN_IPT; i++) {
        int idx = base + i;
        if (idx < n) {
            int p = off + local[i];
            g_rowptr[idx] = p;
            g_cursor[idx] = p;
        }
    }
}

__global__ void scatter_kernel(const int* __restrict__ rows,
                               const int* __restrict__ cols,
                               const float* __restrict__ vals,
                               int nnz) {
    int e = blockIdx.x * blockDim.x + threadIdx.x;
    if (e >= nnz) return;
    int r = rows[e];
    int pos = atomicAdd(&g_cursor[r], 1);
    g_edge[pos] = make_int2(cols[e], __float_as_int(vals[e]));
}

// ---------------------------------------------------------------------------
// pull SpMM (FROZEN round-8 shape): fp16 operand, fp32 accumulation,
// warp per row, 4-wide edge unroll (MLP=4).
// ---------------------------------------------------------------------------
__device__ __forceinline__ float2 h2f_lo(unsigned u) {
    __half2 h = *reinterpret_cast<__half2*>(&u);
    return __half22float2(h);
}

template <bool FUSE>
__global__ void __launch_bounds__(256) spmm_half_kernel(
        const uint2* __restrict__ x,
        uint2* __restrict__ yh,
        const float4* __restrict__ emb,
        const uint2* __restrict__ x1,
        const uint2* __restrict__ x2,
        float4* __restrict__ outf,
        int n) {
    int w = (blockIdx.x * blockDim.x + threadIdx.x) >> 5;
    int lane = threadIdx.x & 31;
    if (w >= n) return;

    int start = g_rowptr[w];
    int end = start + g_deg[w];

    float a0x = 0.f, a0y = 0.f, a0z = 0.f, a0w = 0.f;
    float a1x = 0.f, a1y = 0.f, a1z = 0.f, a1w = 0.f;

    int e = start;
    // 4-wide: issue all 4 gathers before consuming any
    for (; e + 4 <= end; e += 4) {
        int2 e0 = g_edge[e];
        int2 e1 = g_edge[e + 1];
        int2 e2 = g_edge[e + 2];
        int2 e3 = g_edge[e + 3];
        uint2 m0 = __ldg(x + (size_t)e0.x * 32 + lane);
        uint2 m1 = __ldg(x + (size_t)e1.x * 32 + lane);
        uint2 m2 = __ldg(x + (size_t)e2.x * 32 + lane);
        uint2 m3 = __ldg(x + (size_t)e3.x * 32 + lane);
        float v0 = __int_as_float(e0.y);
        float v1 = __int_as_float(e1.y);
        float v2 = __int_as_float(e2.y);
        float v3 = __int_as_float(e3.y);
        {
            float2 fa = h2f_lo(m0.x), fb = h2f_lo(m0.y);
            a0x += v0 * fa.x; a0y += v0 * fa.y; a0z += v0 * fb.x; a0w += v0 * fb.y;
        }
        {
            float2 fa = h2f_lo(m1.x), fb = h2f_lo(m1.y);
            a1x += v1 * fa.x; a1y += v1 * fa.y; a1z += v1 * fb.x; a1w += v1 * fb.y;
        }
        {
            float2 fa = h2f_lo(m2.x), fb = h2f_lo(m2.y);
            a0x += v2 * fa.x; a0y += v2 * fa.y; a0z += v2 * fb.x; a0w += v2 * fb.y;
        }
        {
            float2 fa = h2f_lo(m3.x), fb = h2f_lo(m3.y);
            a1x += v3 * fa.x; a1y += v3 * fa.y; a1z += v3 * fb.x; a1w += v3 * fb.y;
        }
    }
    if (e + 2 <= end) {
        int2 e0 = g_edge[e];
        int2 e1 = g_edge[e + 1];
        uint2 m0 = __ldg(x + (size_t)e0.x * 32 + lane);
        uint2 m1 = __ldg(x + (size_t)e1.x * 32 + lane);
        float v0 = __int_as_float(e0.y);
        float v1 = __int_as_float(e1.y);
        float2 fa = h2f_lo(m0.x), fb = h2f_lo(m0.y);
        a0x += v0 * fa.x; a0y += v0 * fa.y; a0z += v0 * fb.x; a0w += v0 * fb.y;
        float2 fc = h2f_lo(m1.x), fd = h2f_lo(m1.y);
        a1x += v1 * fc.x; a1y += v1 * fc.y; a1z += v1 * fd.x; a1w += v1 * fd.y;
        e += 2;
    }
    if (e < end) {
        int2 e0 = g_edge[e];
        uint2 m0 = __ldg(x + (size_t)e0.x * 32 + lane);
        float v0 = __int_as_float(e0.y);
        float2 fa = h2f_lo(m0.x), fb = h2f_lo(m0.y);
        a0x += v0 * fa.x; a0y += v0 * fa.y; a0z += v0 * fb.x; a0w += v0 * fb.y;
    }

    float rx = a0x + a1x, ry = a0y + a1y, rz = a0z + a1z, rw = a0w + a1w;

    size_t oidx = (size_t)w * 32 + lane;
    if (FUSE) {
        float4 eb = __ldg(emb + oidx);
        uint2 u1 = __ldg(x1 + oidx);
        uint2 u2 = __ldg(x2 + oidx);
        float2 b10 = h2f_lo(u1.x), b11 = h2f_lo(u1.y);
        float2 b20 = h2f_lo(u2.x), b21 = h2f_lo(u2.y);
        float4 o;
        o.x = (rx + eb.x + b10.x + b20.x) * 0.25f;
        o.y = (ry + eb.y + b10.y + b20.y) * 0.25f;
        o.z = (rz + eb.z + b11.x + b21.x) * 0.25f;
        o.w = (rw + eb.w + b11.y + b21.y) * 0.25f;
        outf[oidx] = o;
    } else {
        __half2 ha = __float22half2_rn(make_float2(rx, ry));
        __half2 hb = __float22half2_rn(make_float2(rz, rw));
        uint2 r;
        r.x = *reinterpret_cast<unsigned int*>(&ha);
        r.y = *reinterpret_cast<unsigned int*>(&hb);
        yh[oidx] = r;
    }
}

// ---------------------------------------------------------------------------
extern "C" void kernel_launch(void* const* d_in, const int* in_sizes, int n_in,
                              void* d_out, int out_size) {
    const float* emb  = (const float*)d_in[0];
    const float* vals = (const float*)d_in[1];
    const int*   rows = (const int*)d_in[2];
    const int*   cols = (const int*)d_in[3];
    float* out = (float*)d_out;

    int nnz = in_sizes[1];
    int n   = in_sizes[0] / DN;

    __half* xe; __half* x1; __half* x2;
    cudaGetSymbolAddress((void**)&xe, g_xe);
    cudaGetSymbolAddress((void**)&x1, g_x1);
    cudaGetSymbolAddress((void**)&x2, g_x2);

    const int TB = 256;
    int total4 = in_sizes[0] / 4;
    int nb_scan     = (n + SCAN_CHUNK - 1) / SCAN_CHUNK;
    int deg_blocks  = (n + TB - 1) / TB;
    int edge_blocks = (nnz + TB - 1) / TB;
    int ew_blocks   = (total4 + TB - 1) / TB;
    int spmm_blocks = (n * 32 + TB - 1) / TB;

    // --- CSR build + f2h (5 launches total before the layers) ---
    zero_kernel<<<deg_blocks, TB>>>(n);
    f2h_hist_kernel<<<ew_blocks + edge_blocks, TB>>>(
        (const float4*)emb, (uint2*)xe, total4, ew_blocks, rows, nnz);
    scan_fused_kernel<<<nb_scan, SCAN_BLK>>>(n);
    scatter_kernel<<<edge_blocks, TB>>>(rows, cols, vals, nnz);

    // --- 3 layers (frozen SpMM) ---
    spmm_half_kernel<false><<<spmm_blocks, TB>>>(
        (const uint2*)xe, (uint2*)x1, nullptr, nullptr, nullptr, nullptr, n);
    spmm_half_kernel<false><<<spmm_blocks, TB>>>(
        (const uint2*)x1, (uint2*)x2, nullptr, nullptr, nullptr, nullptr, n);
    spmm_half_kernel<true><<<spmm_blocks, TB>>>(
        (const uint2*)x2, nullptr,
        (const float4*)emb, (const uint2*)x1, (const uint2*)x2,
        (float4*)out, n);
}